// round 17
// baseline (speedup 1.0000x reference)
#include <cuda_runtime.h>
#include <cuda_bf16.h>

#define N_NODES  100000
#define N_EDGES  1200000
#define N_GRAPHS 256
#define SCAN_BLOCKS 98   // ceil(100000/1024); MUST stay < 148 (co-resident)

// ---------------- device scratch (no allocs allowed) ----------------
// Contract: g_deg, g_poolM, g_poolS, g_cnt, g_bar are ZERO on entry to
// kernel_launch (zero-init on module load; scan_kernel re-zeroes g_deg,
// mlp_kernel re-zeroes the rest) -> deterministic graph replay.
__device__ int   g_deg[N_NODES];
__device__ int   g_rowptr[N_NODES + 1];
__device__ int   g_cur[N_NODES];
__device__ int   g_csr[N_EDGES];
__device__ int   g_bsums[SCAN_BLOCKS];
__device__ int   g_bar;
__device__ __align__(16) float g_h1[N_NODES * 64];
__device__ __align__(16) float g_h2[N_NODES * 64];
__device__ __align__(16) float g_poolM[N_GRAPHS * 64];  // sum of mean3 rows
__device__ __align__(16) float g_poolS[N_GRAPHS * 64];  // sum of relu(h2) rows
__device__ int   g_cnt[N_GRAPHS];                       // nodes per graph

// ---------------- CSR build (R15 three-kernel chain) ----------------
__global__ void count_kernel(const int* __restrict__ edge) {
    int e = blockIdx.x * blockDim.x + threadIdx.x;
    if (e < N_EDGES) {
        int dst = edge[N_EDGES + e];
        atomicAdd(&g_deg[dst], 1);
    }
}

__global__ void scan_kernel() {
    __shared__ int s[1024];
    __shared__ int s2[128];
    const int tid = threadIdx.x;
    const int i = blockIdx.x * 1024 + tid;

    int v = (i < N_NODES) ? g_deg[i] : 0;
    s[tid] = v;
    __syncthreads();
    for (int off = 1; off < 1024; off <<= 1) {
        int t = (tid >= off) ? s[tid - off] : 0;
        __syncthreads();
        s[tid] += t;
        __syncthreads();
    }
    int local_excl = s[tid] - v;
    if (tid == 1023) g_bsums[blockIdx.x] = s[1023];

    __threadfence();
    __syncthreads();
    if (tid == 0) {
        atomicAdd(&g_bar, 1);
        while (*(volatile int*)&g_bar < SCAN_BLOCKS) { }
    }
    __syncthreads();
    __threadfence();

    if (tid < 128) s2[tid] = (tid < SCAN_BLOCKS) ? g_bsums[tid] : 0;
    __syncthreads();
    for (int off = 1; off < 128; off <<= 1) {
        int t = (tid < 128 && tid >= off) ? s2[tid - off] : 0;
        __syncthreads();
        if (tid < 128) s2[tid] += t;
        __syncthreads();
    }
    int boff = (blockIdx.x == 0) ? 0 : s2[blockIdx.x - 1];
    if (i < N_NODES) {
        int r = local_excl + boff;
        g_rowptr[i] = r;
        g_cur[i] = r;
        g_deg[i] = 0;
    }
    if (i == 0) g_rowptr[N_NODES] = N_EDGES;
}

__global__ void fill_kernel(const int* __restrict__ edge) {
    int e = blockIdx.x * blockDim.x + threadIdx.x;
    if (e < N_EDGES) {
        int src = edge[e];
        int dst = edge[N_EDGES + e];
        int pos = atomicAdd(&g_cur[dst], 1);
        g_csr[pos] = src;
    }
}

// ---------------- layer 1: x[100k,8] -> g_h1[100k,64], relu ----------------
#define A8_STRIDE 20
__global__ void sage8_kernel(const float* __restrict__ x,
                             const float* __restrict__ Wl,
                             const float* __restrict__ bias,
                             const float* __restrict__ Wr) {
    __shared__ __align__(16) float sA[128 * A8_STRIDE];
    __shared__ float sB[16 * 64];
    __shared__ float sBias[64];

    const int tid = threadIdx.x;
    if (tid < 128) ((float4*)sB)[tid] = ((const float4*)Wl)[tid];
    else           ((float4*)sB)[tid] = ((const float4*)Wr)[tid - 128];
    if (tid < 64) sBias[tid] = bias[tid];

    const int base = blockIdx.x * 128;
    const float4* x4 = (const float4*)x;

    {
        const int lane = tid & 31;
        const int nodeLocal = (tid >> 5) * 16 + (lane >> 1);
        const int p = lane & 1;
        const int node = base + nodeLocal;
        float4 m  = make_float4(0.f, 0.f, 0.f, 0.f);
        float4 sf = make_float4(0.f, 0.f, 0.f, 0.f);
        if (node < N_NODES) {
            int start = g_rowptr[node], end = g_rowptr[node + 1];
            float4 a0 = make_float4(0.f, 0.f, 0.f, 0.f);
            float4 a1 = make_float4(0.f, 0.f, 0.f, 0.f);
            float4 a2 = make_float4(0.f, 0.f, 0.f, 0.f);
            float4 a3 = make_float4(0.f, 0.f, 0.f, 0.f);
            int e = start;
            for (; e + 3 < end; e += 4) {
                int s0 = g_csr[e],     s1 = g_csr[e + 1];
                int s2 = g_csr[e + 2], s3 = g_csr[e + 3];
                float4 v0 = x4[s0 * 2 + p];
                float4 v1 = x4[s1 * 2 + p];
                float4 v2 = x4[s2 * 2 + p];
                float4 v3 = x4[s3 * 2 + p];
                a0.x += v0.x; a0.y += v0.y; a0.z += v0.z; a0.w += v0.w;
                a1.x += v1.x; a1.y += v1.y; a1.z += v1.z; a1.w += v1.w;
                a2.x += v2.x; a2.y += v2.y; a2.z += v2.z; a2.w += v2.w;
                a3.x += v3.x; a3.y += v3.y; a3.z += v3.z; a3.w += v3.w;
            }
            for (; e < end; ++e) {
                float4 v0 = x4[g_csr[e] * 2 + p];
                a0.x += v0.x; a0.y += v0.y; a0.z += v0.z; a0.w += v0.w;
            }
            float inv = 1.0f / (float)max(end - start, 1);
            m.x = (a0.x + a1.x + a2.x + a3.x) * inv;
            m.y = (a0.y + a1.y + a2.y + a3.y) * inv;
            m.z = (a0.z + a1.z + a2.z + a3.z) * inv;
            m.w = (a0.w + a1.w + a2.w + a3.w) * inv;
            sf = x4[node * 2 + p];
        }
        *(float4*)&sA[nodeLocal * A8_STRIDE + p * 4]     = m;
        *(float4*)&sA[nodeLocal * A8_STRIDE + 8 + p * 4] = sf;
    }
    __syncthreads();

    const int tn = tid & 15, tm = tid >> 4;
    float acc[8][4];
#pragma unroll
    for (int i = 0; i < 8; ++i)
#pragma unroll
        for (int j = 0; j < 4; ++j) acc[i][j] = sBias[tn * 4 + j];

#pragma unroll
    for (int k = 0; k < 16; ++k) {
        float4 bv = *(const float4*)&sB[k * 64 + tn * 4];
        float a[8];
#pragma unroll
        for (int i = 0; i < 8; ++i) a[i] = sA[(tm * 8 + i) * A8_STRIDE + k];
#pragma unroll
        for (int i = 0; i < 8; ++i) {
            acc[i][0] += a[i] * bv.x;
            acc[i][1] += a[i] * bv.y;
            acc[i][2] += a[i] * bv.z;
            acc[i][3] += a[i] * bv.w;
        }
    }

    float4* hout4 = (float4*)g_h1;
#pragma unroll
    for (int i = 0; i < 8; ++i) {
        int node = base + tm * 8 + i;
        if (node < N_NODES) {
            float4 o;
            o.x = fmaxf(acc[i][0], 0.0f);
            o.y = fmaxf(acc[i][1], 0.0f);
            o.z = fmaxf(acc[i][2], 0.0f);
            o.w = fmaxf(acc[i][3], 0.0f);
            hout4[node * 16 + tn] = o;
        }
    }
}

// ---------------- layer 2: g_h1 -> g_h2, relu; fused Σh2/cnt pooling ------
// Warp-autonomous GEMM (R8/R11). Epilogue also run-accumulates relu(h2) into
// g_poolS and node counts into g_cnt (batch is sorted).
#define TILE_N64 112
#define A_STRIDE 68   // 272 B rows, 16B-aligned
#define SM64_BYTES ((TILE_N64 * A_STRIDE + 2 * 4096) * 4)   // 63232

__global__ void __launch_bounds__(256) sage64_kernel(
                              const float* __restrict__ Wl,
                              const float* __restrict__ bias,
                              const float* __restrict__ Wr,
                              const int* __restrict__ batch) {
    extern __shared__ float sm64[];
    float* sA  = sm64;                              // [112][68]
    float* sBl = sm64 + TILE_N64 * A_STRIDE;        // [64][64]
    float* sBr = sBl + 4096;                        // [64][64]

    const float* hin = g_h1;
    float* hout      = g_h2;

    const int tid  = threadIdx.x;
    const int base = blockIdx.x * TILE_N64;
    const int warp = tid >> 5, lane = tid & 31;
    const int lr = lane >> 4;
    const int hl = lane & 15;

    {
        const float4* Wl4 = (const float4*)Wl;
        const float4* Wr4 = (const float4*)Wr;
        float4* l4 = (float4*)sBl;
        float4* r4 = (float4*)sBr;
#pragma unroll
        for (int t = 0; t < 4; ++t) {
            l4[tid + t * 256] = Wl4[tid + t * 256];
            r4[tid + t * 256] = Wr4[tid + t * 256];
        }
    }
    __syncthreads();

    const float4* hin4 = (const float4*)hin;
    const int rowBase = warp * 14 + lr * 7;

    for (int it = 0; it < 7; ++it) {
        int nodeLocal = rowBase + it;
        int node = base + nodeLocal;
        float4 m = make_float4(0.f, 0.f, 0.f, 0.f);
        if (node < N_NODES) {
            int start = g_rowptr[node], end = g_rowptr[node + 1];
            float4 a0 = make_float4(0.f, 0.f, 0.f, 0.f);
            float4 a1 = make_float4(0.f, 0.f, 0.f, 0.f);
            float4 a2 = make_float4(0.f, 0.f, 0.f, 0.f);
            float4 a3 = make_float4(0.f, 0.f, 0.f, 0.f);
            int e = start;
            for (; e + 3 < end; e += 4) {
                int s0 = g_csr[e],     s1 = g_csr[e + 1];
                int s2 = g_csr[e + 2], s3 = g_csr[e + 3];
                float4 v0 = hin4[s0 * 16 + hl];
                float4 v1 = hin4[s1 * 16 + hl];
                float4 v2 = hin4[s2 * 16 + hl];
                float4 v3 = hin4[s3 * 16 + hl];
                a0.x += v0.x; a0.y += v0.y; a0.z += v0.z; a0.w += v0.w;
                a1.x += v1.x; a1.y += v1.y; a1.z += v1.z; a1.w += v1.w;
                a2.x += v2.x; a2.y += v2.y; a2.z += v2.z; a2.w += v2.w;
                a3.x += v3.x; a3.y += v3.y; a3.z += v3.z; a3.w += v3.w;
            }
            for (; e < end; ++e) {
                int s0 = g_csr[e];
                float4 v0 = hin4[s0 * 16 + hl];
                a0.x += v0.x; a0.y += v0.y; a0.z += v0.z; a0.w += v0.w;
            }
            float inv = 1.0f / (float)max(end - start, 1);
            m.x = (a0.x + a1.x + a2.x + a3.x) * inv;
            m.y = (a0.y + a1.y + a2.y + a3.y) * inv;
            m.z = (a0.z + a1.z + a2.z + a3.z) * inv;
            m.w = (a0.w + a1.w + a2.w + a3.w) * inv;
        }
        *(float4*)&sA[nodeLocal * A_STRIDE + hl * 4] = m;
    }
    __syncwarp();

    float acc[7][4];
    {
        float4 bb = *(const float4*)&bias[hl * 4];
#pragma unroll
        for (int i = 0; i < 7; ++i) {
            acc[i][0] = bb.x; acc[i][1] = bb.y; acc[i][2] = bb.z; acc[i][3] = bb.w;
        }
    }

#pragma unroll 4
    for (int k = 0; k < 64; k += 2) {
        float4 bv0 = *(const float4*)&sBl[k * 64 + hl * 4];
        float4 bv1 = *(const float4*)&sBl[(k + 1) * 64 + hl * 4];
        float2 a[7];
#pragma unroll
        for (int i = 0; i < 7; ++i)
            a[i] = *(const float2*)&sA[(rowBase + i) * A_STRIDE + k];
#pragma unroll
        for (int i = 0; i < 7; ++i) {
            acc[i][0] += a[i].x * bv0.x; acc[i][1] += a[i].x * bv0.y;
            acc[i][2] += a[i].x * bv0.z; acc[i][3] += a[i].x * bv0.w;
            acc[i][0] += a[i].y * bv1.x; acc[i][1] += a[i].y * bv1.y;
            acc[i][2] += a[i].y * bv1.z; acc[i][3] += a[i].y * bv1.w;
        }
    }
    __syncwarp();

#pragma unroll
    for (int t = 0; t < 7; ++t) {
        int idx = lane + t * 32;
        int nl = idx >> 4, c = idx & 15;
        int nodeLocal = warp * 14 + nl;
        int node = base + nodeLocal;
        float4 v = make_float4(0.f, 0.f, 0.f, 0.f);
        if (node < N_NODES) v = hin4[node * 16 + c];
        *(float4*)&sA[nodeLocal * A_STRIDE + c * 4] = v;
    }
    __syncwarp();

#pragma unroll 4
    for (int k = 0; k < 64; k += 2) {
        float4 bv0 = *(const float4*)&sBr[k * 64 + hl * 4];
        float4 bv1 = *(const float4*)&sBr[(k + 1) * 64 + hl * 4];
        float2 a[7];
#pragma unroll
        for (int i = 0; i < 7; ++i)
            a[i] = *(const float2*)&sA[(rowBase + i) * A_STRIDE + k];
#pragma unroll
        for (int i = 0; i < 7; ++i) {
            acc[i][0] += a[i].x * bv0.x; acc[i][1] += a[i].x * bv0.y;
            acc[i][2] += a[i].x * bv0.z; acc[i][3] += a[i].x * bv0.w;
            acc[i][0] += a[i].y * bv1.x; acc[i][1] += a[i].y * bv1.y;
            acc[i][2] += a[i].y * bv1.z; acc[i][3] += a[i].y * bv1.w;
        }
    }

    // ---- epilogue: store relu(h2) AND run-accumulate g_poolS / g_cnt ----
    float4* hout4 = (float4*)hout;
    int cur = -1, cnt = 0;
    float4 s = make_float4(0.f, 0.f, 0.f, 0.f);
#pragma unroll
    for (int i = 0; i < 7; ++i) {
        int node = base + rowBase + i;
        if (node < N_NODES) {
            float4 o;
            o.x = fmaxf(acc[i][0], 0.f); o.y = fmaxf(acc[i][1], 0.f);
            o.z = fmaxf(acc[i][2], 0.f); o.w = fmaxf(acc[i][3], 0.f);
            hout4[node * 16 + hl] = o;
            int b = batch[node];
            if (b != cur) {
                if (cur >= 0) {
                    float* dS = &g_poolS[cur * 64 + hl * 4];
                    atomicAdd(dS + 0, s.x); atomicAdd(dS + 1, s.y);
                    atomicAdd(dS + 2, s.z); atomicAdd(dS + 3, s.w);
                    if (hl == 0) atomicAdd(&g_cnt[cur], cnt);
                }
                cur = b; cnt = 0;
                s = make_float4(0.f, 0.f, 0.f, 0.f);
            }
            s.x += o.x; s.y += o.y; s.z += o.z; s.w += o.w;
            ++cnt;
        }
    }
    if (cur >= 0) {
        float* dS = &g_poolS[cur * 64 + hl * 4];
        atomicAdd(dS + 0, s.x); atomicAdd(dS + 1, s.y);
        atomicAdd(dS + 2, s.z); atomicAdd(dS + 3, s.w);
        if (hl == 0) atomicAdd(&g_cnt[cur], cnt);
    }
}

// ---------------- layer 3 (linear) mean-gather + pool ---------------------
// QUARTER-WARP per node: 8 lanes (ql) x 8 cols each; 4 nodes in flight/warp;
// edge unroll x4 -> 8 independent LDG.128 per lane. poolM only (poolS/cnt
// are fused into sage64's epilogue).
__global__ void __launch_bounds__(256) pool3_kernel(const int* __restrict__ batch) {
    const int tid = threadIdx.x;
    const int base = blockIdx.x * 128;
    const int warp = tid >> 5, lane = tid & 31;
    const int q = lane >> 3;          // node slot 0..3
    const int ql = lane & 7;          // column group: cols [ql*8, ql*8+8)
    const float4* hin4 = (const float4*)g_h2;

    int cur = -1;
    float4 sM0 = make_float4(0.f, 0.f, 0.f, 0.f);
    float4 sM1 = make_float4(0.f, 0.f, 0.f, 0.f);

    for (int it = 0; it < 4; ++it) {
        int node = base + warp * 16 + it * 4 + q;
        if (node >= N_NODES) break;

        int start = g_rowptr[node], end = g_rowptr[node + 1];
        float4 p0 = make_float4(0.f, 0.f, 0.f, 0.f);
        float4 p1 = make_float4(0.f, 0.f, 0.f, 0.f);
        float4 p2 = make_float4(0.f, 0.f, 0.f, 0.f);
        float4 p3 = make_float4(0.f, 0.f, 0.f, 0.f);
        float4 r0 = make_float4(0.f, 0.f, 0.f, 0.f);
        float4 r1 = make_float4(0.f, 0.f, 0.f, 0.f);
        float4 r2 = make_float4(0.f, 0.f, 0.f, 0.f);
        float4 r3 = make_float4(0.f, 0.f, 0.f, 0.f);
        int e = start;
        for (; e + 3 < end; e += 4) {
            int s0 = g_csr[e],     s1 = g_csr[e + 1];
            int s2 = g_csr[e + 2], s3 = g_csr[e + 3];
            float4 u0 = hin4[s0 * 16 + ql * 2];
            float4 w0 = hin4[s0 * 16 + ql * 2 + 1];
            float4 u1 = hin4[s1 * 16 + ql * 2];
            float4 w1 = hin4[s1 * 16 + ql * 2 + 1];
            float4 u2 = hin4[s2 * 16 + ql * 2];
            float4 w2 = hin4[s2 * 16 + ql * 2 + 1];
            float4 u3 = hin4[s3 * 16 + ql * 2];
            float4 w3 = hin4[s3 * 16 + ql * 2 + 1];
            p0.x += u0.x; p0.y += u0.y; p0.z += u0.z; p0.w += u0.w;
            r0.x += w0.x; r0.y += w0.y; r0.z += w0.z; r0.w += w0.w;
            p1.x += u1.x; p1.y += u1.y; p1.z += u1.z; p1.w += u1.w;
            r1.x += w1.x; r1.y += w1.y; r1.z += w1.z; r1.w += w1.w;
            p2.x += u2.x; p2.y += u2.y; p2.z += u2.z; p2.w += u2.w;
            r2.x += w2.x; r2.y += w2.y; r2.z += w2.z; r2.w += w2.w;
            p3.x += u3.x; p3.y += u3.y; p3.z += u3.z; p3.w += u3.w;
            r3.x += w3.x; r3.y += w3.y; r3.z += w3.z; r3.w += w3.w;
        }
        for (; e < end; ++e) {
            int s0 = g_csr[e];
            float4 u0 = hin4[s0 * 16 + ql * 2];
            float4 w0 = hin4[s0 * 16 + ql * 2 + 1];
            p0.x += u0.x; p0.y += u0.y; p0.z += u0.z; p0.w += u0.w;
            r0.x += w0.x; r0.y += w0.y; r0.z += w0.z; r0.w += w0.w;
        }
        float inv = 1.0f / (float)max(end - start, 1);
        float4 m0, m1;
        m0.x = (p0.x + p1.x + p2.x + p3.x) * inv;
        m0.y = (p0.y + p1.y + p2.y + p3.y) * inv;
        m0.z = (p0.z + p1.z + p2.z + p3.z) * inv;
        m0.w = (p0.w + p1.w + p2.w + p3.w) * inv;
        m1.x = (r0.x + r1.x + r2.x + r3.x) * inv;
        m1.y = (r0.y + r1.y + r2.y + r3.y) * inv;
        m1.z = (r0.z + r1.z + r2.z + r3.z) * inv;
        m1.w = (r0.w + r1.w + r2.w + r3.w) * inv;

        int b = batch[node];
        if (b != cur) {
            if (cur >= 0) {
                float* dM = &g_poolM[cur * 64 + ql * 8];
                atomicAdd(dM + 0, sM0.x); atomicAdd(dM + 1, sM0.y);
                atomicAdd(dM + 2, sM0.z); atomicAdd(dM + 3, sM0.w);
                atomicAdd(dM + 4, sM1.x); atomicAdd(dM + 5, sM1.y);
                atomicAdd(dM + 6, sM1.z); atomicAdd(dM + 7, sM1.w);
            }
            cur = b;
            sM0 = make_float4(0.f, 0.f, 0.f, 0.f);
            sM1 = make_float4(0.f, 0.f, 0.f, 0.f);
        }
        sM0.x += m0.x; sM0.y += m0.y; sM0.z += m0.z; sM0.w += m0.w;
        sM1.x += m1.x; sM1.y += m1.y; sM1.z += m1.z; sM1.w += m1.w;
    }
    if (cur >= 0) {
        float* dM = &g_poolM[cur * 64 + ql * 8];
        atomicAdd(dM + 0, sM0.x); atomicAdd(dM + 1, sM0.y);
        atomicAdd(dM + 2, sM0.z); atomicAdd(dM + 3, sM0.w);
        atomicAdd(dM + 4, sM1.x); atomicAdd(dM + 5, sM1.y);
        atomicAdd(dM + 6, sM1.z); atomicAdd(dM + 7, sM1.w);
    }
}

// ---------------- MLP head: layer-3 GEMM on pooled vectors + classifier ---
__global__ void mlp_kernel(const float* __restrict__ W3l,
                           const float* __restrict__ b3,
                           const float* __restrict__ W3r,
                           const float* __restrict__ Wc1,
                           const float* __restrict__ bc1,
                           const float* __restrict__ Wc2,
                           const float* __restrict__ bc2,
                           float* __restrict__ out) {
    __shared__ float sh[8][64];
    int warp = threadIdx.x >> 5;
    int lane = threadIdx.x & 31;
    int gr = blockIdx.x * 8 + warp;
    if (gr < N_GRAPHS) {
        float c = (float)g_cnt[gr];
        float h0 = c * b3[2 * lane];
        float h1 = c * b3[2 * lane + 1];
#pragma unroll 4
        for (int k = 0; k < 64; ++k) {
            float pm = g_poolM[gr * 64 + k];
            float ps = g_poolS[gr * 64 + k];
            h0 += pm * W3l[k * 64 + 2 * lane]     + ps * W3r[k * 64 + 2 * lane];
            h1 += pm * W3l[k * 64 + 2 * lane + 1] + ps * W3r[k * 64 + 2 * lane + 1];
        }
        sh[warp][2 * lane]     = h0;
        sh[warp][2 * lane + 1] = h1;
        __syncwarp();
        float h = bc1[lane];
#pragma unroll
        for (int k = 0; k < 64; ++k)
            h += sh[warp][k] * Wc1[k * 32 + lane];
        h = fmaxf(h, 0.0f);
        float p = h * Wc2[lane];
#pragma unroll
        for (int off = 16; off > 0; off >>= 1)
            p += __shfl_xor_sync(0xffffffffu, p, off);
        if (lane == 0) out[gr] = p + bc2[0];
        // re-zero replay state (own graph's rows; reads above complete)
        g_poolM[gr * 64 + 2 * lane]     = 0.0f;
        g_poolM[gr * 64 + 2 * lane + 1] = 0.0f;
        g_poolS[gr * 64 + 2 * lane]     = 0.0f;
        g_poolS[gr * 64 + 2 * lane + 1] = 0.0f;
        if (lane == 0) g_cnt[gr] = 0;
    }
    if (blockIdx.x == 0 && threadIdx.x == 0) g_bar = 0;
}

// ---------------- launch ----------------
extern "C" void kernel_launch(void* const* d_in, const int* in_sizes, int n_in,
                              void* d_out, int out_size) {
    const float* x     = (const float*)d_in[0];
    const int*   edge  = (const int*)d_in[1];     // int32 (JAX x64 disabled)
    const int*   batch = (const int*)d_in[2];     // int32
    const float* W1l = (const float*)d_in[3];
    const float* b1  = (const float*)d_in[4];
    const float* W1r = (const float*)d_in[5];
    const float* W2l = (const float*)d_in[6];
    const float* b2  = (const float*)d_in[7];
    const float* W2r = (const float*)d_in[8];
    const float* W3l = (const float*)d_in[9];
    const float* b3  = (const float*)d_in[10];
    const float* W3r = (const float*)d_in[11];
    const float* Wc1 = (const float*)d_in[12];
    const float* bc1 = (const float*)d_in[13];
    const float* Wc2 = (const float*)d_in[14];
    const float* bc2 = (const float*)d_in[15];
    float* out = (float*)d_out;

    cudaFuncSetAttribute(sage64_kernel,
                         cudaFuncAttributeMaxDynamicSharedMemorySize, SM64_BYTES);

    count_kernel<<<(N_EDGES + 255) / 256, 256>>>(edge);            // 1
    scan_kernel<<<SCAN_BLOCKS, 1024>>>();                          // 2
    fill_kernel<<<(N_EDGES + 255) / 256, 256>>>(edge);             // 3

    const int NT8  = (N_NODES + 127) / 128;                // 782
    const int NT64 = (N_NODES + TILE_N64 - 1) / TILE_N64;  // 893
    sage8_kernel<<<NT8, 256>>>(x, W1l, b1, W1r);                   // 4
    sage64_kernel<<<NT64, 256, SM64_BYTES>>>(W2l, b2, W2r, batch); // 5
    pool3_kernel<<<NT8, 256>>>(batch);                             // 6

    mlp_kernel<<<32, 256>>>(W3l, b3, W3r, Wc1, bc1, Wc2, bc2, out);// 7
}